// round 1
// baseline (speedup 1.0000x reference)
#include <cuda_runtime.h>

#define N_NODES 100000
#define N_EDGES 1600000
#define D 64
#define NGRAPH 256
#define EPS 1e-5f

#define SCAN_B 1024
#define NBLK ((N_NODES + SCAN_B - 1) / SCAN_B)   // 98

// ---- scratch (static device globals; no allocation) ----
__device__ int   g_deg_out[N_NODES];
__device__ int   g_deg_in[N_NODES];
__device__ int   g_start[N_NODES + 1];
__device__ int   g_cursor[N_NODES];
__device__ int   g_blocksum[128];
__device__ int   g_blockoff[128];
__device__ int   g_ssrc[N_EDGES];
__device__ float g_sew[N_EDGES];
__device__ float g_h1[N_NODES * D];
__device__ float g_h2[N_NODES * D];
__device__ float g_cnt[NGRAPH];

// ---------------------------------------------------------------- zero
__global__ void k_zero(float* __restrict__ out) {
    int i = blockIdx.x * blockDim.x + threadIdx.x;
    if (i < N_NODES) { g_deg_out[i] = 0; g_deg_in[i] = 0; }
    if (i < NGRAPH) g_cnt[i] = 0.f;
    if (i < NGRAPH * D) out[i] = 0.f;
}

// ---------------------------------------------------------------- degrees
__global__ void k_degree(const int* __restrict__ src, const int* __restrict__ dst) {
    int e = blockIdx.x * blockDim.x + threadIdx.x;
    if (e < N_EDGES) {
        atomicAdd(&g_deg_out[src[e]], 1);
        atomicAdd(&g_deg_in[dst[e]], 1);
    }
}

// ---------------------------------------------------------------- scan (exclusive, over in-degree)
__global__ void k_scan_block() {
    __shared__ int sh[SCAN_B];
    int tid = threadIdx.x;
    int i = blockIdx.x * SCAN_B + tid;
    int v = (i < N_NODES) ? g_deg_in[i] : 0;
    sh[tid] = v;
    __syncthreads();
    for (int off = 1; off < SCAN_B; off <<= 1) {
        int x = (tid >= off) ? sh[tid - off] : 0;
        __syncthreads();
        sh[tid] += x;
        __syncthreads();
    }
    if (i < N_NODES) g_start[i] = sh[tid] - v;      // exclusive partial
    if (tid == SCAN_B - 1) g_blocksum[blockIdx.x] = sh[tid];
}

__global__ void k_scan_top() {
    __shared__ int sh[128];
    int tid = threadIdx.x;
    int v = (tid < NBLK) ? g_blocksum[tid] : 0;
    sh[tid] = v;
    __syncthreads();
    for (int off = 1; off < 128; off <<= 1) {
        int x = (tid >= off) ? sh[tid - off] : 0;
        __syncthreads();
        sh[tid] += x;
        __syncthreads();
    }
    if (tid < NBLK) g_blockoff[tid] = sh[tid] - v;
}

__global__ void k_scan_add() {
    int i = blockIdx.x * blockDim.x + threadIdx.x;
    if (i < N_NODES) {
        int s = g_start[i] + g_blockoff[i / SCAN_B];
        g_start[i] = s;
        g_cursor[i] = s;
    }
    if (i == 0) g_start[N_NODES] = N_EDGES;
}

// ---------------------------------------------------------------- bucket edges by dst
// also folds source-side norm into the edge weight: ew_eff = ew * rsqrt(max(out_deg[src],1))
__global__ void k_bucket(const int* __restrict__ src, const int* __restrict__ dst,
                         const float* __restrict__ ew) {
    int e = blockIdx.x * blockDim.x + threadIdx.x;
    if (e >= N_EDGES) return;
    int s = src[e];
    int d = dst[e];
    int p = atomicAdd(&g_cursor[d], 1);
    g_ssrc[p] = s;
    g_sew[p]  = ew[e] * rsqrtf(fmaxf((float)g_deg_out[s], 1.f));
}

// ---------------------------------------------------------------- fused layer:
// pull-aggregate into SMEM, scale by rsqrt(in_deg), 64x64x64 GEMM, +b, ReLU, BN, ReLU
__global__ __launch_bounds__(256) void k_layer(
    const float* __restrict__ hin,
    const float* __restrict__ W,  const float* __restrict__ b,
    const float* __restrict__ gamma, const float* __restrict__ beta,
    const float* __restrict__ rm,    const float* __restrict__ rv,
    float* __restrict__ hout)
{
    __shared__ float Ash[64 * 66];   // padded rows (66) : conflict-free
    __shared__ float Wsh[64 * 64];

    int t = threadIdx.x;
    int lane = t & 31;
    int w = t >> 5;                  // warp id 0..7
    int nb = blockIdx.x * 64;

    // stage W into SMEM
    for (int j = t; j < 1024; j += 256)
        ((float4*)Wsh)[j] = ((const float4*)W)[j];

    // aggregation: each warp handles 8 nodes, 2 dims/lane via float2
    const float2* hp = (const float2*)hin;
    #pragma unroll 1
    for (int i = 0; i < 8; i++) {
        int row = w * 8 + i;
        int n = nb + row;
        float2 acc = make_float2(0.f, 0.f);
        if (n < N_NODES) {
            int e0 = g_start[n];
            int e1 = g_start[n + 1];
            for (int e = e0; e < e1; e++) {
                int s = g_ssrc[e];
                float we = g_sew[e];
                float2 hv = hp[s * 32 + lane];   // 256B coalesced per edge
                acc.x += hv.x * we;
                acc.y += hv.y * we;
            }
            float ri = rsqrtf(fmaxf((float)g_deg_in[n], 1.f));
            acc.x *= ri; acc.y *= ri;
        }
        *(float2*)&Ash[row * 66 + 2 * lane] = acc;
    }
    __syncthreads();

    // GEMM: 4 nodes x 4 dims per thread
    int d0 = (t & 15) * 4;
    int n0 = (t >> 4) * 4;
    float acc[4][4];
    #pragma unroll
    for (int i = 0; i < 4; i++)
        #pragma unroll
        for (int j = 0; j < 4; j++) acc[i][j] = 0.f;

    #pragma unroll 8
    for (int k = 0; k < 64; k++) {
        float4 wv = *(const float4*)&Wsh[k * 64 + d0];
        #pragma unroll
        for (int i = 0; i < 4; i++) {
            float av = Ash[(n0 + i) * 66 + k];
            acc[i][0] += av * wv.x;
            acc[i][1] += av * wv.y;
            acc[i][2] += av * wv.z;
            acc[i][3] += av * wv.w;
        }
    }

    // epilogue: +b, ReLU, BN(eval), ReLU
    float4 b4  = *(const float4*)&b[d0];
    float4 g4  = *(const float4*)&gamma[d0];
    float4 be4 = *(const float4*)&beta[d0];
    float4 rm4 = *(const float4*)&rm[d0];
    float4 rv4 = *(const float4*)&rv[d0];
    float s0 = rsqrtf(rv4.x + EPS) * g4.x;
    float s1 = rsqrtf(rv4.y + EPS) * g4.y;
    float s2 = rsqrtf(rv4.z + EPS) * g4.z;
    float s3 = rsqrtf(rv4.w + EPS) * g4.w;

    #pragma unroll
    for (int i = 0; i < 4; i++) {
        int n = nb + n0 + i;
        if (n >= N_NODES) continue;
        float4 o;
        o.x = fmaxf(acc[i][0] + b4.x, 0.f);
        o.y = fmaxf(acc[i][1] + b4.y, 0.f);
        o.z = fmaxf(acc[i][2] + b4.z, 0.f);
        o.w = fmaxf(acc[i][3] + b4.w, 0.f);
        o.x = fmaxf((o.x - rm4.x) * s0 + be4.x, 0.f);
        o.y = fmaxf((o.y - rm4.y) * s1 + be4.y, 0.f);
        o.z = fmaxf((o.z - rm4.z) * s2 + be4.z, 0.f);
        o.w = fmaxf((o.w - rm4.w) * s3 + be4.w, 0.f);
        ((float4*)hout)[n * 16 + (d0 >> 2)] = o;
    }
}

// ---------------------------------------------------------------- readout (mean over sorted node2graph)
__global__ void k_readout(const int* __restrict__ n2g, float* __restrict__ out) {
    const int NP = 8;  // nodes per thread-group pass
    int t = blockIdx.x * blockDim.x + threadIdx.x;
    int group = t >> 4;
    int q = t & 15;
    int nbase = group * NP;
    if (nbase >= N_NODES) return;

    float4 acc = make_float4(0.f, 0.f, 0.f, 0.f);
    int curg = n2g[nbase];
    int runlen = 0;
    for (int i = 0; i < NP; i++) {
        int n = nbase + i;
        if (n >= N_NODES) break;
        int g = n2g[n];
        if (g != curg) {
            float* o = out + curg * 64 + q * 4;
            atomicAdd(o + 0, acc.x); atomicAdd(o + 1, acc.y);
            atomicAdd(o + 2, acc.z); atomicAdd(o + 3, acc.w);
            if (q == 0) atomicAdd(&g_cnt[curg], (float)runlen);
            acc = make_float4(0.f, 0.f, 0.f, 0.f);
            curg = g; runlen = 0;
        }
        float4 v = ((const float4*)g_h2)[n * 16 + q];
        acc.x += v.x; acc.y += v.y; acc.z += v.z; acc.w += v.w;
        runlen++;
    }
    float* o = out + curg * 64 + q * 4;
    atomicAdd(o + 0, acc.x); atomicAdd(o + 1, acc.y);
    atomicAdd(o + 2, acc.z); atomicAdd(o + 3, acc.w);
    if (q == 0) atomicAdd(&g_cnt[curg], (float)runlen);
}

__global__ void k_div(float* __restrict__ out) {
    int i = blockIdx.x * blockDim.x + threadIdx.x;
    if (i < NGRAPH * D) out[i] = out[i] / fmaxf(g_cnt[i >> 6], 1.f);
}

// ---------------------------------------------------------------- launch
extern "C" void kernel_launch(void* const* d_in, const int* in_sizes, int n_in,
                              void* d_out, int out_size) {
    const float* h   = (const float*)d_in[0];
    const float* ew  = (const float*)d_in[1];
    const int*   src = (const int*)d_in[2];
    const int*   dst = (const int*)d_in[3];
    const int*   n2g = (const int*)d_in[4];
    const float* W1 = (const float*)d_in[5];
    const float* b1 = (const float*)d_in[6];
    const float* gamma1 = (const float*)d_in[7];
    const float* beta1  = (const float*)d_in[8];
    const float* rm1 = (const float*)d_in[9];
    const float* rv1 = (const float*)d_in[10];
    const float* W2 = (const float*)d_in[11];
    const float* b2 = (const float*)d_in[12];
    const float* gamma2 = (const float*)d_in[13];
    const float* beta2  = (const float*)d_in[14];
    const float* rm2 = (const float*)d_in[15];
    const float* rv2 = (const float*)d_in[16];
    float* out = (float*)d_out;

    float* h1; cudaGetSymbolAddress((void**)&h1, g_h1);
    float* h2; cudaGetSymbolAddress((void**)&h2, g_h2);

    const int TB = 256;
    int gN = (N_NODES + TB - 1) / TB;
    int gE = (N_EDGES + TB - 1) / TB;

    k_zero<<<gN, TB>>>(out);
    k_degree<<<gE, TB>>>(src, dst);
    k_scan_block<<<NBLK, SCAN_B>>>();
    k_scan_top<<<1, 128>>>();
    k_scan_add<<<gN, TB>>>();
    k_bucket<<<gE, TB>>>(src, dst, ew);

    int gL = (N_NODES + 63) / 64;
    k_layer<<<gL, 256>>>(h,  W1, b1, gamma1, beta1, rm1, rv1, h1);
    k_layer<<<gL, 256>>>(h1, W2, b2, gamma2, beta2, rm2, rv2, h2);

    int gR = ((N_NODES + 7) / 8 * 16 + TB - 1) / TB;
    k_readout<<<gR, TB>>>(n2g, out);
    k_div<<<(NGRAPH * D + TB - 1) / TB, TB>>>(out);
}